// round 9
// baseline (speedup 1.0000x reference)
#include <cuda_runtime.h>

// out[r] = dot(W1[i1[r]], W2[i2[r]]) + b1[i1[r]] + b2[i2[r]]
// R1 shape (one warp per row) but with NORMAL-path global loads (not .nc)
// + L2 evict_last cache policy: test whether the .nc path was inserting
// gathered lines into L2 at streaming priority, preventing retention of the
// 15.5MB working set across graph replays.

#define BATCH 16384
#define EMBED 128  // 32 float4 per row

__device__ __forceinline__ unsigned long long mk_policy_evict_last() {
    unsigned long long pol;
    asm volatile("createpolicy.fractional.L2::evict_last.b64 %0, 1.0;" : "=l"(pol));
    return pol;
}

__device__ __forceinline__ float4 ld_el4(const float4* p, unsigned long long pol) {
    float4 v;
    asm volatile("ld.global.L2::cache_hint.v4.f32 {%0,%1,%2,%3}, [%4], %5;"
                 : "=f"(v.x), "=f"(v.y), "=f"(v.z), "=f"(v.w)
                 : "l"(p), "l"(pol));
    return v;
}

__device__ __forceinline__ float ld_el1(const float* p, unsigned long long pol) {
    float v;
    asm volatile("ld.global.L2::cache_hint.f32 %0, [%1], %2;"
                 : "=f"(v) : "l"(p), "l"(pol));
    return v;
}

__global__ __launch_bounds__(256)
void fused_embed_dot_kernel(const int* __restrict__ i1,
                            const int* __restrict__ i2,
                            const float* __restrict__ W1,
                            const float* __restrict__ W2,
                            const float* __restrict__ b1,
                            const float* __restrict__ b2,
                            float* __restrict__ out) {
    int warp_global = (blockIdx.x * blockDim.x + threadIdx.x) >> 5;
    int lane = threadIdx.x & 31;

    unsigned long long pol = mk_policy_evict_last();

    int idx1 = i1[warp_global];
    int idx2 = i2[warp_global];

    // Bias gathers issued early — overlap with row gathers (normal path,
    // evict_last retention).
    float bv1 = ld_el1(&b1[idx1], pol);
    float bv2 = ld_el1(&b2[idx2], pol);

    const float4* r1 = reinterpret_cast<const float4*>(W1 + (size_t)idx1 * EMBED);
    const float4* r2 = reinterpret_cast<const float4*>(W2 + (size_t)idx2 * EMBED);

    // Two independent LDG.128 per lane, normal L2 insertion + evict_last.
    float4 a = ld_el4(&r1[lane], pol);
    float4 b = ld_el4(&r2[lane], pol);

    float acc = a.x * b.x;
    acc = fmaf(a.y, b.y, acc);
    acc = fmaf(a.z, b.z, acc);
    acc = fmaf(a.w, b.w, acc);

    // Warp butterfly reduction.
    #pragma unroll
    for (int off = 16; off > 0; off >>= 1)
        acc += __shfl_xor_sync(0xFFFFFFFFu, acc, off);

    if (lane == 0)
        out[warp_global] = acc + bv1 + bv2;
}

extern "C" void kernel_launch(void* const* d_in, const int* in_sizes, int n_in,
                              void* d_out, int out_size) {
    const int*   i1 = (const int*)d_in[0];
    const int*   i2 = (const int*)d_in[1];
    const float* W1 = (const float*)d_in[2];
    const float* W2 = (const float*)d_in[3];
    const float* b1 = (const float*)d_in[4];
    const float* b2 = (const float*)d_in[5];
    float* out = (float*)d_out;

    // 16384 rows * 32 threads / 256 = 2048 blocks (best measured grid).
    fused_embed_dot_kernel<<<(BATCH * 32) / 256, 256>>>(i1, i2, W1, W2, b1, b2, out);
}